// round 10
// baseline (speedup 1.0000x reference)
#include <cuda_runtime.h>
#include <cuda_fp16.h>
#include <stdint.h>

// ---------------- problem constants ----------------
#define N_ITEMS 8192
#define D_IN    1024
#define E_OUT   1024
#define K_TYPES 8
#define OUT_COLS (E_OUT + K_TYPES)   // 1032

// ---------------- GEMM tiling ----------------
#define BM 128
#define BN 128
#define BK 32
#define NITER (D_IN / BK)             // 32
#define NSTAGE 3
#define MAX_TILES (N_ITEMS / BM + K_TYPES)   // 72

#define A_STRIDE 80
#define B_STRIDE 272
#define SZA (BM * A_STRIDE)           // 10240
#define SZB (BK * B_STRIDE)           // 8704
#define DYN_SMEM (NSTAGE * (2 * SZA + SZB))   // 87552

// setup kernel layout: block 0 = route, 1..4096 = convert x, 4097..8192 = convert W
#define XBLOCKS 4096
#define WBLOCKS 4096
#define SETUP_BLOCKS (1 + XBLOCKS + WBLOCKS)

// ---------------- device scratch ----------------
__device__ int g_perm[N_ITEMS];
__device__ int g_tile_type[MAX_TILES];
__device__ int g_tile_base[MAX_TILES];
__device__ int g_tile_rows[MAX_TILES];
__device__ int g_num_tiles;

__device__ __half g_xh[(size_t)N_ITEMS * D_IN];
__device__ __half g_xl[(size_t)N_ITEMS * D_IN];
__device__ __half g_wh[(size_t)K_TYPES * D_IN * E_OUT];  // [k][d][e]

// ---------------- PTX helpers ----------------
__device__ __forceinline__ uint32_t smem_u32(const void* p) {
    uint32_t a;
    asm("{ .reg .u64 t; cvta.to.shared.u64 t, %1; cvt.u32.u64 %0, t; }" : "=r"(a) : "l"(p));
    return a;
}

#define CP_ASYNC16(dst, src, sz) \
    asm volatile("cp.async.cg.shared.global [%0], [%1], 16, %2;" \
                 :: "r"(dst), "l"(src), "r"(sz) : "memory")
#define CP_COMMIT() asm volatile("cp.async.commit_group;" ::: "memory")
#define CP_WAIT(n)  asm volatile("cp.async.wait_group %0;" :: "n"(n) : "memory")

__device__ __forceinline__ void ldmatrix_x4(uint32_t& r0, uint32_t& r1, uint32_t& r2,
                                            uint32_t& r3, uint32_t addr) {
    asm volatile("ldmatrix.sync.aligned.m8n8.x4.shared.b16 {%0,%1,%2,%3}, [%4];"
                 : "=r"(r0), "=r"(r1), "=r"(r2), "=r"(r3) : "r"(addr));
}
__device__ __forceinline__ void ldmatrix_x4_trans(uint32_t& r0, uint32_t& r1, uint32_t& r2,
                                                  uint32_t& r3, uint32_t addr) {
    asm volatile("ldmatrix.sync.aligned.m8n8.x4.trans.shared.b16 {%0,%1,%2,%3}, [%4];"
                 : "=r"(r0), "=r"(r1), "=r"(r2), "=r"(r3) : "r"(addr));
}
__device__ __forceinline__ void mma16816_f32(float* c, const uint32_t* a, const uint32_t* b) {
    asm volatile(
        "mma.sync.aligned.m16n8k16.row.col.f32.f16.f16.f32 "
        "{%0,%1,%2,%3}, {%4,%5,%6,%7}, {%8,%9}, {%0,%1,%2,%3};"
        : "+f"(c[0]), "+f"(c[1]), "+f"(c[2]), "+f"(c[3])
        : "r"(a[0]), "r"(a[1]), "r"(a[2]), "r"(a[3]), "r"(b[0]), "r"(b[1]));
}
__device__ __forceinline__ void mma16816_f16(uint32_t* c, const uint32_t* a, const uint32_t* b) {
    asm volatile(
        "mma.sync.aligned.m16n8k16.row.col.f16.f16.f16.f16 "
        "{%0,%1}, {%2,%3,%4,%5}, {%6,%7}, {%0,%1};"
        : "+r"(c[0]), "+r"(c[1])
        : "r"(a[0]), "r"(a[1]), "r"(a[2]), "r"(a[3]), "r"(b[0]), "r"(b[1]));
}

// ---------------- type_ids dtype detection (per-warp, deterministic) ----------------
__device__ __forceinline__ int detect_is64(const int* tid32) {
    int v = tid32[2 * (threadIdx.x & 31) + 1];
    unsigned int ballot = __ballot_sync(0xFFFFFFFFu, v == 0);
    return ballot == 0xFFFFFFFFu;
}
__device__ __forceinline__ int load_type(const int* tid32, int n, int is64) {
    return is64 ? tid32[2 * n] : tid32[n];
}

// ---------------- fused setup: route (block 0, scheduled first) + converts --------
__global__ void __launch_bounds__(256) setup_kernel(
    const float* __restrict__ x, const float* __restrict__ W, const int* tid32)
{
    const int bid = blockIdx.x;
    const int tid = threadIdx.x;

    if (bid == 0) {
        // ---- route: count + scan + scatter, 256 threads ----
        __shared__ int cnt[K_TYPES];
        __shared__ int base[K_TYPES];
        const int lane = tid & 31;
        const int is64 = detect_is64(tid32);

        if (tid < K_TYPES) cnt[tid] = 0;
        __syncthreads();

        int k[32];
#pragma unroll
        for (int i = 0; i < 32; i++)
            k[i] = load_type(tid32, tid + i * 256, is64);

#pragma unroll
        for (int i = 0; i < 32; i++) {
            unsigned m = __match_any_sync(0xFFFFFFFFu, k[i]);
            if (lane == __ffs(m) - 1) atomicAdd(&cnt[k[i]], __popc(m));
        }
        __syncthreads();

        if (tid == 0) {
            int off = 0, nt = 0;
            for (int t = 0; t < K_TYPES; t++) {
                base[t] = off;
                int c = cnt[t];
                for (int q = 0; q < c; q += BM) {
                    g_tile_type[nt] = t;
                    g_tile_base[nt] = off + q;
                    g_tile_rows[nt] = min(BM, c - q);
                    nt++;
                }
                off += c;
            }
            g_num_tiles = nt;
        }
        __syncthreads();

        if (tid < K_TYPES) cnt[tid] = base[tid];
        __syncthreads();

        // warp-aggregated scatter (cross-warp order nondeterministic; outputs
        // are permutation-invariant, so the final result stays deterministic)
#pragma unroll
        for (int i = 0; i < 32; i++) {
            const int n = tid + i * 256;
            unsigned m = __match_any_sync(0xFFFFFFFFu, k[i]);
            const int leader = __ffs(m) - 1;
            const int rank = __popc(m & ((1u << lane) - 1u));
            int b = 0;
            if (lane == leader) b = atomicAdd(&cnt[k[i]], __popc(m));
            b = __shfl_sync(0xFFFFFFFFu, b, leader);
            g_perm[b + rank] = n;
        }
        return;
    }

    if (bid <= XBLOCKS) {
        // ---- convert x -> xh, xl ----
        size_t i = ((size_t)(bid - 1) * 256 + tid) * 8;
        float4 v0 = *(const float4*)(x + i);
        float4 v1 = *(const float4*)(x + i + 4);
        float v[8] = {v0.x, v0.y, v0.z, v0.w, v1.x, v1.y, v1.z, v1.w};
        __half h[8], l[8];
#pragma unroll
        for (int j = 0; j < 8; j++) {
            h[j] = __float2half_rn(v[j]);
            l[j] = __float2half_rn(v[j] - __half2float(h[j]));
        }
        *(uint4*)(g_xh + i) = *(uint4*)h;
        *(uint4*)(g_xl + i) = *(uint4*)l;
        return;
    }

    // ---- convert W -> Wh ----
    {
        size_t i = ((size_t)(bid - 1 - XBLOCKS) * 256 + tid) * 8;
        float4 v0 = *(const float4*)(W + i);
        float4 v1 = *(const float4*)(W + i + 4);
        float v[8] = {v0.x, v0.y, v0.z, v0.w, v1.x, v1.y, v1.z, v1.w};
        __half h[8];
#pragma unroll
        for (int j = 0; j < 8; j++) h[j] = __float2half_rn(v[j]);
        *(uint4*)(g_wh + i) = *(uint4*)h;
    }
}

// ---------------- grouped fp16 mma.sync GEMM ----------------
// xh term: f32 accumulate. xl term: f16 accumulate (2x rate if legacy f32-acc
// HMMA is half-rate); xl partials are ~5e-4 of output scale so f16 acc error
// is ~3e-6 relative — far below the 2.08e-4 W-rounding floor.
__global__ void __launch_bounds__(256, 2) gemm_mma_kernel(
    const float* __restrict__ bias, float* __restrict__ out)
{
    const int tile = blockIdx.x;
    if (tile >= g_num_tiles) return;

    extern __shared__ __align__(16) char dynsm[];
    char* smAh = dynsm;
    char* smAl = dynsm + NSTAGE * SZA;
    char* smB  = dynsm + 2 * NSTAGE * SZA;
    __shared__ int   ridx[BM];
    __shared__ float bs[BN];

    const int tid  = threadIdx.x;
    const int lane = tid & 31;
    const int wid  = tid >> 5;
    const int warp_m = wid & 3;
    const int warp_n = wid >> 2;

    const int ktype = g_tile_type[tile];
    const int rbase = g_tile_base[tile];
    const int rows  = g_tile_rows[tile];
    const int col0  = blockIdx.y * BN;

    if (tid < BM) ridx[tid] = (tid < rows) ? g_perm[rbase + tid] : -1;
    if (tid < BN) bs[tid] = bias[(size_t)ktype * E_OUT + col0 + tid];
    __syncthreads();

    // fused one-hot tail
    if (blockIdx.y == 0 && tid < BM) {
        const int row = ridx[tid];
        if (row >= 0) {
            float v[8] = {0.f, 0.f, 0.f, 0.f, 0.f, 0.f, 0.f, 0.f};
            v[ktype] = 1.0f;
            float* p = out + (size_t)row * OUT_COLS + E_OUT;
            *(float4*)(p)     = make_float4(v[0], v[1], v[2], v[3]);
            *(float4*)(p + 4) = make_float4(v[4], v[5], v[6], v[7]);
        }
    }

    // ---- per-thread cp.async descriptors ----
    const int ar = tid >> 1;
    const int arow = ridx[ar];
    const uint32_t asz = (arow >= 0) ? 16u : 0u;
    const size_t aoff = (size_t)(arow >= 0 ? arow : 0) * D_IN + (tid & 1) * 16;
    const uint32_t ahDst0 = smem_u32(smAh) + (uint32_t)(ar * A_STRIDE + (tid & 1) * 32);
    const uint32_t alDst0 = smem_u32(smAl) + (uint32_t)(ar * A_STRIDE + (tid & 1) * 32);
    const int br = tid >> 3;
    const int bc = tid & 7;
    const size_t boff = (size_t)(ktype * D_IN) * E_OUT + (size_t)br * E_OUT + col0 + bc * 8;
    const uint32_t bDst0 = smem_u32(smB) + (uint32_t)(br * B_STRIDE + bc * 16);

    auto stage_load = [&](int s) {
        const uint32_t buf = (uint32_t)(s % NSTAGE);
        const int kk = s * BK;
        const __half* ah = g_xh + aoff + kk;
        const __half* al = g_xl + aoff + kk;
        const __half* bsrc = g_wh + boff + (size_t)kk * E_OUT;
        const uint32_t ahD = ahDst0 + buf * SZA;
        const uint32_t alD = alDst0 + buf * SZA;
        const uint32_t bD  = bDst0 + buf * SZB;
        CP_ASYNC16(ahD,      ah,     asz);
        CP_ASYNC16(ahD + 16, ah + 8, asz);
        CP_ASYNC16(alD,      al,     asz);
        CP_ASYNC16(alD + 16, al + 8, asz);
        CP_ASYNC16(bD,       bsrc,      16u);
        CP_ASYNC16(bD + 128, bsrc + 64, 16u);
    };

    const uint32_t aFragOff =
        (uint32_t)((warp_m * 32 + (lane & 15)) * A_STRIDE + (lane >> 4) * 16);
    const uint32_t ahBase = smem_u32(smAh) + aFragOff;
    const uint32_t alBase = smem_u32(smAl) + aFragOff;
    const uint32_t bBase = smem_u32(smB) +
        (uint32_t)((lane & 15) * B_STRIDE + (lane >> 4) * 16 + warp_n * 128);

    float    acch[2][8][4];     // xh term, f32 accumulate
    uint32_t accl[2][8][2];     // xl term, f16x2 accumulate
#pragma unroll
    for (int mi = 0; mi < 2; mi++)
#pragma unroll
        for (int ni = 0; ni < 8; ni++) {
#pragma unroll
            for (int j = 0; j < 4; j++) acch[mi][ni][j] = 0.0f;
            accl[mi][ni][0] = 0u;
            accl[mi][ni][1] = 0u;
        }

    stage_load(0); CP_COMMIT();
    stage_load(1); CP_COMMIT();

    for (int s = 0; s < NITER; s++) {
        CP_WAIT(1);
        __syncthreads();
        if (s + 2 < NITER) { stage_load(s + 2); CP_COMMIT(); }

        const uint32_t buf = (uint32_t)(s % NSTAGE);
        const uint32_t ahB = ahBase + buf * SZA;
        const uint32_t alB = alBase + buf * SZA;
        const uint32_t bB  = bBase + buf * SZB;
#pragma unroll
        for (int kst = 0; kst < 2; kst++) {
            uint32_t af[2][4];
            uint32_t bfr[4][2];
            // --- xh pass (f32 acc) ---
#pragma unroll
            for (int mi = 0; mi < 2; mi++)
                ldmatrix_x4(af[mi][0], af[mi][1], af[mi][2], af[mi][3],
                            ahB + mi * 16 * A_STRIDE + kst * 32);
#pragma unroll
            for (int nh = 0; nh < 2; nh++) {
#pragma unroll
                for (int nj = 0; nj < 2; nj++)
                    ldmatrix_x4_trans(bfr[2 * nj][0], bfr[2 * nj][1],
                                      bfr[2 * nj + 1][0], bfr[2 * nj + 1][1],
                                      bB + kst * 16 * B_STRIDE + nh * 64 + nj * 32);
#pragma unroll
                for (int mi = 0; mi < 2; mi++)
#pragma unroll
                    for (int ni = 0; ni < 4; ni++)
                        mma16816_f32(acch[mi][nh * 4 + ni], af[mi], bfr[ni]);
            }
            // --- xl pass (f16 acc, 2x rate) ---
#pragma unroll
            for (int mi = 0; mi < 2; mi++)
                ldmatrix_x4(af[mi][0], af[mi][1], af[mi][2], af[mi][3],
                            alB + mi * 16 * A_STRIDE + kst * 32);
#pragma unroll
            for (int nh = 0; nh < 2; nh++) {
#pragma unroll
                for (int nj = 0; nj < 2; nj++)
                    ldmatrix_x4_trans(bfr[2 * nj][0], bfr[2 * nj][1],
                                      bfr[2 * nj + 1][0], bfr[2 * nj + 1][1],
                                      bB + kst * 16 * B_STRIDE + nh * 64 + nj * 32);
#pragma unroll
                for (int mi = 0; mi < 2; mi++)
#pragma unroll
                    for (int ni = 0; ni < 4; ni++)
                        mma16816_f16(accl[mi][nh * 4 + ni], af[mi], bfr[ni]);
            }
        }
    }

    // ---- epilogue: combine terms + bias + gathered store ----
#pragma unroll
    for (int mi = 0; mi < 2; mi++) {
        const int r0 = warp_m * 32 + mi * 16 + (lane >> 2);
        const int r1 = r0 + 8;
        const int g0 = ridx[r0];
        const int g1 = ridx[r1];
#pragma unroll
        for (int ni = 0; ni < 8; ni++) {
            const int col = warp_n * 64 + ni * 8 + (lane & 3) * 2;
            const float b0 = bs[col], b1 = bs[col + 1];
            const __half2 l0 = *(__half2*)&accl[mi][ni][0];
            const __half2 l1 = *(__half2*)&accl[mi][ni][1];
            if (g0 >= 0) {
                float2 v = {acch[mi][ni][0] + __low2float(l0) + b0,
                            acch[mi][ni][1] + __high2float(l0) + b1};
                *(float2*)(out + (size_t)g0 * OUT_COLS + col0 + col) = v;
            }
            if (g1 >= 0) {
                float2 v = {acch[mi][ni][2] + __low2float(l1) + b0,
                            acch[mi][ni][3] + __high2float(l1) + b1};
                *(float2*)(out + (size_t)g1 * OUT_COLS + col0 + col) = v;
            }
        }
    }
}

// ---------------- launch ----------------
extern "C" void kernel_launch(void* const* d_in, const int* in_sizes, int n_in,
                              void* d_out, int out_size) {
    const float* x     = (const float*)d_in[0];
    const int*   tid32 = (const int*)d_in[1];
    const float* W     = (const float*)d_in[2];
    const float* b     = (const float*)d_in[3];
    float* out = (float*)d_out;

    cudaFuncSetAttribute(gemm_mma_kernel, cudaFuncAttributeMaxDynamicSharedMemorySize,
                         DYN_SMEM);

    setup_kernel<<<SETUP_BLOCKS, 256>>>(x, W, tid32);

    dim3 grid(MAX_TILES, E_OUT / BN);
    gemm_mma_kernel<<<grid, 256, DYN_SMEM>>>(b, out);
}

// round 11
// speedup vs baseline: 1.0368x; 1.0368x over previous
#include <cuda_runtime.h>
#include <cuda_fp16.h>
#include <stdint.h>

// ---------------- problem constants ----------------
#define N_ITEMS 8192
#define D_IN    1024
#define E_OUT   1024
#define K_TYPES 8
#define OUT_COLS (E_OUT + K_TYPES)   // 1032

// ---------------- GEMM tiling ----------------
#define BM 128
#define BN 128
#define BK 32
#define NITER (D_IN / BK)             // 32
#define NSTAGE 3
#define MAX_TILES (N_ITEMS / BM + K_TYPES)   // 72

#define A_STRIDE 80
#define B_STRIDE 272
#define SZA (BM * A_STRIDE)           // 10240
#define SZB (BK * B_STRIDE)           // 8704
#define DYN_SMEM (NSTAGE * (2 * SZA + SZB))   // 87552

// setup kernel layout: block 0 = route, 1..4096 = convert x, 4097..8192 = convert W
#define XBLOCKS 4096
#define WBLOCKS 4096
#define SETUP_BLOCKS (1 + XBLOCKS + WBLOCKS)

// ---------------- device scratch ----------------
__device__ int g_perm[N_ITEMS];
__device__ int g_tile_type[MAX_TILES];
__device__ int g_tile_base[MAX_TILES];
__device__ int g_tile_rows[MAX_TILES];
__device__ int g_num_tiles;

__device__ __half g_xh[(size_t)N_ITEMS * D_IN];
__device__ __half g_xl[(size_t)N_ITEMS * D_IN];
__device__ __half g_wh[(size_t)K_TYPES * D_IN * E_OUT];  // [k][d][e]

// ---------------- PTX helpers ----------------
__device__ __forceinline__ uint32_t smem_u32(const void* p) {
    uint32_t a;
    asm("{ .reg .u64 t; cvta.to.shared.u64 t, %1; cvt.u32.u64 %0, t; }" : "=r"(a) : "l"(p));
    return a;
}

#define CP_ASYNC16(dst, src, sz) \
    asm volatile("cp.async.cg.shared.global [%0], [%1], 16, %2;" \
                 :: "r"(dst), "l"(src), "r"(sz) : "memory")
#define CP_COMMIT() asm volatile("cp.async.commit_group;" ::: "memory")
#define CP_WAIT(n)  asm volatile("cp.async.wait_group %0;" :: "n"(n) : "memory")

__device__ __forceinline__ void ldmatrix_x4(uint32_t& r0, uint32_t& r1, uint32_t& r2,
                                            uint32_t& r3, uint32_t addr) {
    asm volatile("ldmatrix.sync.aligned.m8n8.x4.shared.b16 {%0,%1,%2,%3}, [%4];"
                 : "=r"(r0), "=r"(r1), "=r"(r2), "=r"(r3) : "r"(addr));
}
__device__ __forceinline__ void ldmatrix_x4_trans(uint32_t& r0, uint32_t& r1, uint32_t& r2,
                                                  uint32_t& r3, uint32_t addr) {
    asm volatile("ldmatrix.sync.aligned.m8n8.x4.trans.shared.b16 {%0,%1,%2,%3}, [%4];"
                 : "=r"(r0), "=r"(r1), "=r"(r2), "=r"(r3) : "r"(addr));
}
__device__ __forceinline__ void mma16816(float* c, const uint32_t* a, const uint32_t* b) {
    asm volatile(
        "mma.sync.aligned.m16n8k16.row.col.f32.f16.f16.f32 "
        "{%0,%1,%2,%3}, {%4,%5,%6,%7}, {%8,%9}, {%0,%1,%2,%3};"
        : "+f"(c[0]), "+f"(c[1]), "+f"(c[2]), "+f"(c[3])
        : "r"(a[0]), "r"(a[1]), "r"(a[2]), "r"(a[3]), "r"(b[0]), "r"(b[1]));
}

// ---------------- type_ids dtype detection (per-warp, deterministic) ----------------
__device__ __forceinline__ int detect_is64(const int* tid32) {
    int v = tid32[2 * (threadIdx.x & 31) + 1];
    unsigned int ballot = __ballot_sync(0xFFFFFFFFu, v == 0);
    return ballot == 0xFFFFFFFFu;
}
__device__ __forceinline__ int load_type(const int* tid32, int n, int is64) {
    return is64 ? tid32[2 * n] : tid32[n];
}

// ---------------- fused setup: route (block 0, first wave) + converts ------------
__global__ void __launch_bounds__(256) setup_kernel(
    const float* __restrict__ x, const float* __restrict__ W, const int* tid32)
{
    const int bid = blockIdx.x;
    const int tid = threadIdx.x;

    if (bid == 0) {
        // ---- route: count + scan + scatter, 256 threads ----
        __shared__ int cnt[K_TYPES];
        __shared__ int base[K_TYPES];
        const int lane = tid & 31;
        const int is64 = detect_is64(tid32);

        if (tid < K_TYPES) cnt[tid] = 0;
        __syncthreads();

        int k[32];
#pragma unroll
        for (int i = 0; i < 32; i++)
            k[i] = load_type(tid32, tid + i * 256, is64);

#pragma unroll
        for (int i = 0; i < 32; i++) {
            unsigned m = __match_any_sync(0xFFFFFFFFu, k[i]);
            if (lane == __ffs(m) - 1) atomicAdd(&cnt[k[i]], __popc(m));
        }
        __syncthreads();

        if (tid == 0) {
            int off = 0, nt = 0;
            for (int t = 0; t < K_TYPES; t++) {
                base[t] = off;
                int c = cnt[t];
                for (int q = 0; q < c; q += BM) {
                    g_tile_type[nt] = t;
                    g_tile_base[nt] = off + q;
                    g_tile_rows[nt] = min(BM, c - q);
                    nt++;
                }
                off += c;
            }
            g_num_tiles = nt;
        }
        __syncthreads();

        if (tid < K_TYPES) cnt[tid] = base[tid];
        __syncthreads();

        // warp-aggregated scatter (cross-warp order nondeterministic; outputs
        // are permutation-invariant, so the final result stays deterministic)
#pragma unroll
        for (int i = 0; i < 32; i++) {
            const int n = tid + i * 256;
            unsigned m = __match_any_sync(0xFFFFFFFFu, k[i]);
            const int leader = __ffs(m) - 1;
            const int rank = __popc(m & ((1u << lane) - 1u));
            int b = 0;
            if (lane == leader) b = atomicAdd(&cnt[k[i]], __popc(m));
            b = __shfl_sync(0xFFFFFFFFu, b, leader);
            g_perm[b + rank] = n;
        }
        return;
    }

    if (bid <= XBLOCKS) {
        // ---- convert x -> xh, xl ----
        size_t i = ((size_t)(bid - 1) * 256 + tid) * 8;
        float4 v0 = *(const float4*)(x + i);
        float4 v1 = *(const float4*)(x + i + 4);
        float v[8] = {v0.x, v0.y, v0.z, v0.w, v1.x, v1.y, v1.z, v1.w};
        __half h[8], l[8];
#pragma unroll
        for (int j = 0; j < 8; j++) {
            h[j] = __float2half_rn(v[j]);
            l[j] = __float2half_rn(v[j] - __half2float(h[j]));
        }
        *(uint4*)(g_xh + i) = *(uint4*)h;
        *(uint4*)(g_xl + i) = *(uint4*)l;
        return;
    }

    // ---- convert W -> Wh ----
    {
        size_t i = ((size_t)(bid - 1 - XBLOCKS) * 256 + tid) * 8;
        float4 v0 = *(const float4*)(W + i);
        float4 v1 = *(const float4*)(W + i + 4);
        float v[8] = {v0.x, v0.y, v0.z, v0.w, v1.x, v1.y, v1.z, v1.w};
        __half h[8];
#pragma unroll
        for (int j = 0; j < 8; j++) h[j] = __float2half_rn(v[j]);
        *(uint4*)(g_wh + i) = *(uint4*)h;
    }
}

// ---------------- grouped fp16 mma.sync GEMM (round-9 proven: 116.5us) -----------
__global__ void __launch_bounds__(256, 2) gemm_mma_kernel(
    const float* __restrict__ bias, float* __restrict__ out)
{
    const int tile = blockIdx.x;
    if (tile >= g_num_tiles) return;

    extern __shared__ __align__(16) char dynsm[];
    char* smAh = dynsm;
    char* smAl = dynsm + NSTAGE * SZA;
    char* smB  = dynsm + 2 * NSTAGE * SZA;
    __shared__ int   ridx[BM];
    __shared__ float bs[BN];

    const int tid  = threadIdx.x;
    const int lane = tid & 31;
    const int wid  = tid >> 5;
    const int warp_m = wid & 3;
    const int warp_n = wid >> 2;

    const int ktype = g_tile_type[tile];
    const int rbase = g_tile_base[tile];
    const int rows  = g_tile_rows[tile];
    const int col0  = blockIdx.y * BN;

    if (tid < BM) ridx[tid] = (tid < rows) ? g_perm[rbase + tid] : -1;
    if (tid < BN) bs[tid] = bias[(size_t)ktype * E_OUT + col0 + tid];
    __syncthreads();

    // fused one-hot tail: y==0 CTAs write cols [E_OUT, E_OUT+8)
    if (blockIdx.y == 0 && tid < BM) {
        const int row = ridx[tid];
        if (row >= 0) {
            float v[8] = {0.f, 0.f, 0.f, 0.f, 0.f, 0.f, 0.f, 0.f};
            v[ktype] = 1.0f;
            float* p = out + (size_t)row * OUT_COLS + E_OUT;
            *(float4*)(p)     = make_float4(v[0], v[1], v[2], v[3]);
            *(float4*)(p + 4) = make_float4(v[4], v[5], v[6], v[7]);
        }
    }

    // ---- per-thread cp.async descriptors ----
    const int ar = tid >> 1;
    const int arow = ridx[ar];
    const uint32_t asz = (arow >= 0) ? 16u : 0u;
    const size_t aoff = (size_t)(arow >= 0 ? arow : 0) * D_IN + (tid & 1) * 16;
    const uint32_t ahDst0 = smem_u32(smAh) + (uint32_t)(ar * A_STRIDE + (tid & 1) * 32);
    const uint32_t alDst0 = smem_u32(smAl) + (uint32_t)(ar * A_STRIDE + (tid & 1) * 32);
    const int br = tid >> 3;
    const int bc = tid & 7;
    const size_t boff = (size_t)(ktype * D_IN) * E_OUT + (size_t)br * E_OUT + col0 + bc * 8;
    const uint32_t bDst0 = smem_u32(smB) + (uint32_t)(br * B_STRIDE + bc * 16);

    auto stage_load = [&](int s) {
        const uint32_t buf = (uint32_t)(s % NSTAGE);
        const int kk = s * BK;
        const __half* ah = g_xh + aoff + kk;
        const __half* al = g_xl + aoff + kk;
        const __half* bsrc = g_wh + boff + (size_t)kk * E_OUT;
        const uint32_t ahD = ahDst0 + buf * SZA;
        const uint32_t alD = alDst0 + buf * SZA;
        const uint32_t bD  = bDst0 + buf * SZB;
        CP_ASYNC16(ahD,      ah,     asz);
        CP_ASYNC16(ahD + 16, ah + 8, asz);
        CP_ASYNC16(alD,      al,     asz);
        CP_ASYNC16(alD + 16, al + 8, asz);
        CP_ASYNC16(bD,       bsrc,      16u);
        CP_ASYNC16(bD + 128, bsrc + 64, 16u);
    };

    const uint32_t aFragOff =
        (uint32_t)((warp_m * 32 + (lane & 15)) * A_STRIDE + (lane >> 4) * 16);
    const uint32_t ahBase = smem_u32(smAh) + aFragOff;
    const uint32_t alBase = smem_u32(smAl) + aFragOff;
    const uint32_t bBase = smem_u32(smB) +
        (uint32_t)((lane & 15) * B_STRIDE + (lane >> 4) * 16 + warp_n * 128);

    float acc[2][8][4];
#pragma unroll
    for (int mi = 0; mi < 2; mi++)
#pragma unroll
        for (int ni = 0; ni < 8; ni++)
#pragma unroll
            for (int j = 0; j < 4; j++) acc[mi][ni][j] = 0.0f;

    stage_load(0); CP_COMMIT();
    stage_load(1); CP_COMMIT();

    for (int s = 0; s < NITER; s++) {
        CP_WAIT(1);
        __syncthreads();
        if (s + 2 < NITER) { stage_load(s + 2); CP_COMMIT(); }

        const uint32_t buf = (uint32_t)(s % NSTAGE);
        const uint32_t ahB = ahBase + buf * SZA;
        const uint32_t alB = alBase + buf * SZA;
        const uint32_t bB  = bBase + buf * SZB;
#pragma unroll
        for (int kst = 0; kst < 2; kst++) {
            uint32_t bfr[8][2];
#pragma unroll
            for (int nj = 0; nj < 4; nj++)
                ldmatrix_x4_trans(bfr[2 * nj][0], bfr[2 * nj][1],
                                  bfr[2 * nj + 1][0], bfr[2 * nj + 1][1],
                                  bB + kst * 16 * B_STRIDE + nj * 32);
            uint32_t afh[2][4], afl[2][4];
#pragma unroll
            for (int mi = 0; mi < 2; mi++)
                ldmatrix_x4(afh[mi][0], afh[mi][1], afh[mi][2], afh[mi][3],
                            ahB + mi * 16 * A_STRIDE + kst * 32);
#pragma unroll
            for (int mi = 0; mi < 2; mi++)
                ldmatrix_x4(afl[mi][0], afl[mi][1], afl[mi][2], afl[mi][3],
                            alB + mi * 16 * A_STRIDE + kst * 32);
#pragma unroll
            for (int mi = 0; mi < 2; mi++)
#pragma unroll
                for (int ni = 0; ni < 8; ni++)
                    mma16816(acc[mi][ni], afh[mi], bfr[ni]);
#pragma unroll
            for (int mi = 0; mi < 2; mi++)
#pragma unroll
                for (int ni = 0; ni < 8; ni++)
                    mma16816(acc[mi][ni], afl[mi], bfr[ni]);
        }
    }

    // ---- epilogue: bias + gathered store ----
#pragma unroll
    for (int mi = 0; mi < 2; mi++) {
        const int r0 = warp_m * 32 + mi * 16 + (lane >> 2);
        const int r1 = r0 + 8;
        const int g0 = ridx[r0];
        const int g1 = ridx[r1];
#pragma unroll
        for (int ni = 0; ni < 8; ni++) {
            const int col = warp_n * 64 + ni * 8 + (lane & 3) * 2;
            const float b0 = bs[col], b1 = bs[col + 1];
            if (g0 >= 0) {
                float2 v = {acc[mi][ni][0] + b0, acc[mi][ni][1] + b1};
                *(float2*)(out + (size_t)g0 * OUT_COLS + col0 + col) = v;
            }
            if (g1 >= 0) {
                float2 v = {acc[mi][ni][2] + b0, acc[mi][ni][3] + b1};
                *(float2*)(out + (size_t)g1 * OUT_COLS + col0 + col) = v;
            }
        }
    }
}

// ---------------- launch ----------------
extern "C" void kernel_launch(void* const* d_in, const int* in_sizes, int n_in,
                              void* d_out, int out_size) {
    const float* x     = (const float*)d_in[0];
    const int*   tid32 = (const int*)d_in[1];
    const float* W     = (const float*)d_in[2];
    const float* b     = (const float*)d_in[3];
    float* out = (float*)d_out;

    cudaFuncSetAttribute(gemm_mma_kernel, cudaFuncAttributeMaxDynamicSharedMemorySize,
                         DYN_SMEM);

    setup_kernel<<<SETUP_BLOCKS, 256>>>(x, W, tid32);

    dim3 grid(MAX_TILES, E_OUT / BN);
    gemm_mma_kernel<<<grid, 256, DYN_SMEM>>>(b, out);
}